// round 10
// baseline (speedup 1.0000x reference)
#include <cuda_runtime.h>
#include <cuda_bf16.h>
#include <mma.h>
#include <cstdint>

using namespace nvcuda;

#define SQ 2048
#define NB 8
#define EMB 1024
#define RTOT (SQ*NB)
#define G4 (4*EMB)

#define GF_GELU   1
#define GF_CSKIP  2
#define GF_KCLAMP 4

typedef __nv_bfloat16 bf16;

// ---------------- device scratch (static; no allocation allowed) ----------------
__device__ float g_G    [(size_t)RTOT*G4];
__device__ float g_rnn  [(size_t)RTOT*EMB];
__device__ float g_hmid [(size_t)RTOT*EMB];
__device__ float g_vsc  [(size_t)RTOT*EMB];
__device__ float g_qpre [(size_t)RTOT*EMB];
__device__ float g_scores[(size_t)NB*SQ*SQ];
__device__ float g_h2   [(size_t)RTOT*EMB];
__device__ float g_res  [(size_t)RTOT*EMB];
__device__ float g_bias4[G4];
__device__ float g_op   [2*EMB];
__device__ float g_qsg  [EMB];
__device__ float g_ksg  [EMB];
__device__ float g_vsg  [EMB];
__device__ float g_hbuf [NB*EMB];
__device__ int   g_bar;

__device__ __align__(256) bf16 g_xlnh [(size_t)RTOT*EMB];
__device__ __align__(256) bf16 g_xlnl [(size_t)RTOT*EMB];
__device__ __align__(256) bf16 g_Wihh [(size_t)G4*EMB];
__device__ __align__(256) bf16 g_Wihl [(size_t)G4*EMB];
__device__ __align__(256) bf16 g_hmidh[(size_t)RTOT*EMB];
__device__ __align__(256) bf16 g_hmidl[(size_t)RTOT*EMB];
__device__ __align__(256) bf16 g_qsch [(size_t)RTOT*EMB];
__device__ __align__(256) bf16 g_qscl [(size_t)RTOT*EMB];
__device__ __align__(256) bf16 g_ksch [(size_t)RTOT*EMB];
__device__ __align__(256) bf16 g_kscl [(size_t)RTOT*EMB];
__device__ __align__(256) bf16 g_xffh [(size_t)RTOT*EMB];
__device__ __align__(256) bf16 g_xffl [(size_t)RTOT*EMB];
__device__ __align__(256) bf16 g_vTh  [(size_t)NB*EMB*SQ];
__device__ __align__(256) bf16 g_vTl  [(size_t)NB*EMB*SQ];
__device__ __align__(256) bf16 g_wh   [(size_t)NB*SQ*SQ];
__device__ __align__(256) bf16 g_wl   [(size_t)NB*SQ*SQ];
__device__ __align__(256) bf16 g_qlWh [(size_t)EMB*EMB];
__device__ __align__(256) bf16 g_qlWl [(size_t)EMB*EMB];
__device__ __align__(256) bf16 g_bmWh [(size_t)EMB*EMB];
__device__ __align__(256) bf16 g_bmWl [(size_t)EMB*EMB];

__device__ __forceinline__ float sigm(float x){ return 1.0f/(1.0f + expf(-x)); }

// ---------------- prep ----------------
__global__ void prep_kernel(const float* __restrict__ bih, const float* __restrict__ bhh,
                            const float* __restrict__ qs, const float* __restrict__ ksp){
    int i = blockIdx.x*256 + threadIdx.x;
    if (i < G4) g_bias4[i] = bih[i] + bhh[i];
    if (i < EMB){
        g_qsg[i] = sigm(qs[i]); g_ksg[i] = sigm(ksp[i]);
        #pragma unroll
        for (int b = 0; b < NB; b++) g_hbuf[i + b*EMB] = 0.f;
    }
    if (i == 0) g_bar = 0;
}

__global__ void op_gemm_kernel(const float* __restrict__ vsp, const float* __restrict__ opW,
                               const float* __restrict__ opb){
    __shared__ float vo[EMB];
    int tid = threadIdx.x;
    for (int i = tid; i < EMB; i += 256) vo[i] = sigm(vsp[i]);
    __syncthreads();
    int j = blockIdx.x*256 + tid;
    float acc = 0.f;
    const float* w = opW + (size_t)j*EMB;
    for (int e = 0; e < EMB; e += 4){
        float4 wv = *(const float4*)(w + e);
        acc += wv.x*vo[e] + wv.y*vo[e+1] + wv.z*vo[e+2] + wv.w*vo[e+3];
    }
    g_op[j] = acc + opb[j];
}

__global__ void vsg_kernel(){
    int i = blockIdx.x*256 + threadIdx.x;
    if (i < EMB) g_vsg[i] = sigm(g_op[EMB + i]) * tanhf(g_op[i]);
}

// fp32 -> bf16 hi/lo split
__global__ void split_kernel(const float* __restrict__ src, bf16* __restrict__ hi,
                             bf16* __restrict__ lo, int n){
    int i = blockIdx.x*256 + threadIdx.x;
    if (i < n){
        float v = src[i];
        bf16 h = __float2bfloat16(v);
        hi[i] = h; lo[i] = __float2bfloat16(v - __bfloat162float(h));
    }
}

// ---------------- block reductions ----------------
__device__ __forceinline__ float bsum(float v, float* buf){
    #pragma unroll
    for (int o = 16; o; o >>= 1) v += __shfl_xor_sync(0xffffffffu, v, o);
    int w = threadIdx.x >> 5;
    if ((threadIdx.x & 31) == 0) buf[w] = v;
    __syncthreads();
    if (threadIdx.x == 0){ float s = 0.f; for (int i = 0; i < 8; i++) s += buf[i]; buf[0] = s; }
    __syncthreads();
    float r = buf[0]; __syncthreads();
    return r;
}
__device__ __forceinline__ float bmax(float v, float* buf){
    #pragma unroll
    for (int o = 16; o; o >>= 1) v = fmaxf(v, __shfl_xor_sync(0xffffffffu, v, o));
    int w = threadIdx.x >> 5;
    if ((threadIdx.x & 31) == 0) buf[w] = v;
    __syncthreads();
    if (threadIdx.x == 0){ float s = buf[0]; for (int i = 1; i < 8; i++) s = fmaxf(s, buf[i]); buf[0] = s; }
    __syncthreads();
    float r = buf[0]; __syncthreads();
    return r;
}

// ---------------- layer norm: 3 outputs share stats; each may emit f32 and/or bf16 pair ----------------
__global__ void __launch_bounds__(256) ln_kernel(const float* __restrict__ in,
    float* f1, bf16* h1, bf16* l1, const float* g1, const float* b1, const float* s1,
    float* f2, bf16* h2, bf16* l2, const float* g2, const float* b2, const float* s2,
    float* f3, bf16* h3, bf16* l3, const float* g3, const float* b3, const float* s3){
    __shared__ float buf[8];
    size_t row = blockIdx.x;
    int tid = threadIdx.x, e = tid*4;
    float4 x = *(const float4*)(in + row*EMB + e);
    float m = bsum(x.x + x.y + x.z + x.w, buf) * (1.f/EMB);
    float d0 = x.x - m, d1 = x.y - m, d2 = x.z - m, d3 = x.w - m;
    float v = bsum(d0*d0 + d1*d1 + d2*d2 + d3*d3, buf) * (1.f/EMB);
    float rstd = rsqrtf(v + 1e-12f);
    #define EMIT(f,h,l,g,b,s) if (g){ \
        float4 gv = *(const float4*)((g)+e); float4 bv = *(const float4*)((b)+e); \
        float4 y; y.x = d0*rstd*gv.x + bv.x; y.y = d1*rstd*gv.y + bv.y; \
        y.z = d2*rstd*gv.z + bv.z; y.w = d3*rstd*gv.w + bv.w; \
        if (s){ float4 sv = *(const float4*)((s)+e); y.x*=sv.x; y.y*=sv.y; y.z*=sv.z; y.w*=sv.w; } \
        if (f) *(float4*)((f) + row*EMB + e) = y; \
        if (h){ bf16 p0=__float2bfloat16(y.x), p1=__float2bfloat16(y.y); \
                bf16 p2=__float2bfloat16(y.z), p3=__float2bfloat16(y.w); \
                *(__nv_bfloat162*)((h)+row*EMB+e)   = __halves2bfloat162(p0,p1); \
                *(__nv_bfloat162*)((h)+row*EMB+e+2) = __halves2bfloat162(p2,p3); \
                *(__nv_bfloat162*)((l)+row*EMB+e)   = __halves2bfloat162( \
                    __float2bfloat16(y.x-__bfloat162float(p0)), __float2bfloat16(y.y-__bfloat162float(p1))); \
                *(__nv_bfloat162*)((l)+row*EMB+e+2) = __halves2bfloat162( \
                    __float2bfloat16(y.z-__bfloat162float(p2)), __float2bfloat16(y.w-__bfloat162float(p3))); } }
    EMIT(f1,h1,l1,g1,b1,s1); EMIT(f2,h2,l2,g2,b2,s2); EMIT(f3,h3,l3,g3,b3,s3);
    #undef EMIT
}

// ---------------- causal softmax -> bf16 pair, zero-fill to 256 boundary ----------------
__global__ void __launch_bounds__(256) softmax_kernel(const float* __restrict__ sc,
        bf16* __restrict__ whi, bf16* __restrict__ wlo){
    __shared__ float buf[8];
    int blk = blockIdx.x;
    int s = blk & (SQ-1);
    const float* row = sc + (size_t)blk*SQ;
    int n = s + 1;
    int fill = ((s >> 8) + 1) << 8;
    float vals[8];
    float mx = -1e30f;
    int cnt = 0;
    for (int k = threadIdx.x; k < n; k += 256){ float v = row[k]; vals[cnt++] = v; mx = fmaxf(mx, v); }
    mx = bmax(mx, buf);
    float sm = 0.f;
    for (int i = 0; i < cnt; i++){ float e = expf(vals[i] - mx); vals[i] = e; sm += e; }
    sm = bsum(sm, buf);
    float inv = 1.f/sm;
    bf16* wh = whi + (size_t)blk*SQ;
    bf16* wl = wlo + (size_t)blk*SQ;
    cnt = 0;
    for (int k = threadIdx.x; k < fill; k += 256){
        float v = (k < n) ? vals[cnt++]*inv : 0.f;
        bf16 h = __float2bfloat16(v);
        wh[k] = h; wl[k] = __float2bfloat16(v - __bfloat162float(h));
    }
}

// ---------------- v transpose: [s][b][e] f32 -> [b][e][s] bf16 pair ----------------
__global__ void transpose_v(const float* __restrict__ vsc, bf16* __restrict__ vTh,
                            bf16* __restrict__ vTl){
    __shared__ float t[32][33];
    int b = blockIdx.z;
    int e0 = blockIdx.x*32, s0 = blockIdx.y*32;
    int x = threadIdx.x, y0 = threadIdx.y;
    for (int yy = y0; yy < 32; yy += 8)
        t[yy][x] = vsc[((size_t)(s0+yy)*NB + b)*EMB + e0 + x];
    __syncthreads();
    for (int yy = y0; yy < 32; yy += 8){
        float v = t[x][yy];
        size_t o = (size_t)b*EMB*SQ + (size_t)(e0+yy)*SQ + s0 + x;
        bf16 h = __float2bfloat16(v);
        vTh[o] = h; vTl[o] = __float2bfloat16(v - __bfloat162float(h));
    }
}

// ---------------- split-bf16 GEMM: C = alpha*(A@B^T)[+bias][gelu][+add] ----------------
// block tile 256x128x32, 8 warps of 64x64, cp.async double buffer
__device__ __forceinline__ void cpa16(bf16* dst, const bf16* src){
    uint32_t d = (uint32_t)__cvta_generic_to_shared(dst);
    asm volatile("cp.async.cg.shared.global [%0], [%1], 16;" :: "r"(d), "l"(src));
}

__global__ void __launch_bounds__(256,1) gemm_kernel(
    const bf16* __restrict__ Ah, const bf16* __restrict__ Al, long long lda, long long sAz,
    const bf16* __restrict__ Bh, const bf16* __restrict__ Bl, long long ldb, long long sBz,
    float* __restrict__ C, long long ldc, long long sCz,
    int M, int N, int K,
    const float* __restrict__ bias, const float* __restrict__ addp,
    long long ldadd, long long sAddz, float alpha, int flags){
    extern __shared__ bf16 sm[];
    int m0 = blockIdx.y*256, n0 = blockIdx.x*128;
    if ((flags & GF_CSKIP) && n0 > m0 + 255) return;
    int Keff = (flags & GF_KCLAMP) ? min(K, m0 + 256) : K;
    int nkt = Keff >> 5;

    Ah += (size_t)blockIdx.z*sAz; Al += (size_t)blockIdx.z*sAz;
    Bh += (size_t)blockIdx.z*sBz; Bl += (size_t)blockIdx.z*sBz;
    C  += (size_t)blockIdx.z*sCz;
    if (addp) addp += (size_t)blockIdx.z*sAddz;

    int tid = threadIdx.x, warpId = tid >> 5, lane = tid & 31;
    int wm = warpId >> 1, wn = warpId & 1;

    wmma::fragment<wmma::accumulator,16,16,16,float> acc[4][4];
    #pragma unroll
    for (int i=0;i<4;i++)
        #pragma unroll
        for (int j=0;j<4;j++) wmma::fill_fragment(acc[i][j], 0.f);

    auto loadg = [&](int kt){
        int k0 = kt << 5, s = kt & 1;
        bf16* ash = sm + s*10240;
        bf16* asl = sm + 20480 + s*10240;
        bf16* bsh = sm + 40960 + s*5120;
        bf16* bsl = sm + 51200 + s*5120;
        #pragma unroll
        for (int i=0;i<4;i++){ int id = tid + i*256; int r = id>>2, c = (id&3)*8;
            cpa16(ash + r*40 + c, Ah + (size_t)(m0+r)*lda + k0 + c);
            cpa16(asl + r*40 + c, Al + (size_t)(m0+r)*lda + k0 + c); }
        #pragma unroll
        for (int i=0;i<2;i++){ int id = tid + i*256; int r = id>>2, c = (id&3)*8;
            cpa16(bsh + r*40 + c, Bh + (size_t)(n0+r)*ldb + k0 + c);
            cpa16(bsl + r*40 + c, Bl + (size_t)(n0+r)*ldb + k0 + c); }
        asm volatile("cp.async.commit_group;");
    };

    loadg(0);
    for (int kt = 0; kt < nkt; ++kt){
        if (kt + 1 < nkt){ loadg(kt+1); asm volatile("cp.async.wait_group 1;"); }
        else             { asm volatile("cp.async.wait_group 0;"); }
        __syncthreads();
        int s = kt & 1;
        const bf16* ash = sm + s*10240;
        const bf16* asl = sm + 20480 + s*10240;
        const bf16* bsh = sm + 40960 + s*5120;
        const bf16* bsl = sm + 51200 + s*5120;
        #pragma unroll
        for (int ks = 0; ks < 2; ++ks){
            wmma::fragment<wmma::matrix_b,16,16,16,bf16,wmma::col_major> bhf[4], blf[4];
            #pragma unroll
            for (int in=0;in<4;in++){
                int rr = (wn*64 + in*16)*40 + ks*16;
                wmma::load_matrix_sync(bhf[in], bsh + rr, 40);
                wmma::load_matrix_sync(blf[in], bsl + rr, 40);
            }
            #pragma unroll
            for (int im=0;im<4;im++){
                wmma::fragment<wmma::matrix_a,16,16,16,bf16,wmma::row_major> af, alf;
                int rr = (wm*64 + im*16)*40 + ks*16;
                wmma::load_matrix_sync(af,  ash + rr, 40);
                wmma::load_matrix_sync(alf, asl + rr, 40);
                #pragma unroll
                for (int in=0;in<4;in++){
                    wmma::mma_sync(acc[im][in], af,  bhf[in], acc[im][in]);
                    wmma::mma_sync(acc[im][in], af,  blf[in], acc[im][in]);
                    wmma::mma_sync(acc[im][in], alf, bhf[in], acc[im][in]);
                }
            }
        }
        __syncthreads();
    }

    // epilogue: stage 16 rows x 64 cols per warp
    float* stg = (float*)sm + warpId*(16*68);
    #pragma unroll
    for (int im=0;im<4;im++){
        __syncwarp();
        #pragma unroll
        for (int in=0;in<4;in++)
            wmma::store_matrix_sync(stg + in*16, acc[im][in], 68, wmma::mem_row_major);
        __syncwarp();
        int rbase = m0 + wm*64 + im*16;
        #pragma unroll 2
        for (int i = 0; i < 16; i++){
            int grow = rbase + i;
            #pragma unroll
            for (int hf = 0; hf < 2; hf++){
                int gcol = n0 + wn*64 + hf*32 + lane;
                float v = stg[i*68 + hf*32 + lane] * alpha;
                if (bias) v += __ldg(bias + gcol);
                if (flags & GF_GELU) v = v * (1.f/(1.f + expf(-1.702f*v)));
                if (addp) v += addp[(size_t)grow*ldadd + gcol];
                C[(size_t)grow*ldc + gcol] = v;
            }
        }
    }
}

// ---------------- persistent LSTM: 128 blocks x 256 threads ----------------
union __align__(16) F4U { float4 f; unsigned long long u[2]; };
union U64F2 { unsigned long long u; float2 f; };
__device__ __forceinline__ void ffma2(unsigned long long& acc, unsigned long long a, unsigned long long b){
    asm("fma.rn.f32x2 %0, %1, %2, %0;" : "+l"(acc) : "l"(a), "l"(b));
}

#define WSTR 1044
#define HSTR 1036
#define LSTM_SMEM ((32*WSTR + 8*HSTR + 256)*4)

__global__ void __launch_bounds__(256,1) lstm_kernel(const float* __restrict__ Whh){
    extern __shared__ float smf[];
    float* wsm = smf;
    float* hsm = smf + 32*WSTR;
    float* red = hsm + 8*HSTR;

    int tid = threadIdx.x;
    int c0 = blockIdx.x*8;
    int r = tid >> 3, b = tid & 7;

    for (int idx = tid; idx < 32*256; idx += 256){
        int rr = idx >> 8, k4 = idx & 255;
        int gate = rr >> 3, j = rr & 7;
        *(float4*)(wsm + rr*WSTR + k4*4) =
            *(const float4*)(Whh + ((size_t)(gate*1024 + c0 + j))*1024 + k4*4);
    }

    float cst = 0.f;
    int uj = tid >> 3, ub = tid & 7;

    const float* wp = wsm + r*WSTR;
    const float* hp = hsm + b*HSTR;

    for (int t = 0; t < SQ; ++t){
        float gi=0.f, gf=0.f, gg=0.f, go=0.f;
        if (tid < 64){
            const float* Gp = g_G + ((size_t)t*NB + ub)*G4 + c0 + uj;
            gi = __ldcs(Gp); gf = __ldcs(Gp+1024); gg = __ldcs(Gp+2048); go = __ldcs(Gp+3072);
        }
        for (int idx = tid; idx < 2048; idx += 256){
            int hb = idx >> 8, k4 = idx & 255;
            float4 hv = __ldcg((const float4*)(g_hbuf + hb*EMB + k4*4));
            *(float4*)(hsm + hb*HSTR + k4*4) = hv;
        }
        __syncthreads();

        U64F2 acc; acc.f = make_float2(0.f, 0.f);
        #pragma unroll 4
        for (int k = 0; k < 1024; k += 4){
            F4U wv = *(const F4U*)(wp + k);
            F4U hv = *(const F4U*)(hp + k);
            ffma2(acc.u, wv.u[0], hv.u[0]);
            ffma2(acc.u, wv.u[1], hv.u[1]);
        }
        red[r*8 + b] = acc.f.x + acc.f.y;
        __syncthreads();

        if (tid < 64){
            float xi = red[(uj     )*8 + ub] + gi;
            float xf = red[(8 + uj )*8 + ub] + gf;
            float xg = red[(16 + uj)*8 + ub] + gg;
            float xo = red[(24 + uj)*8 + ub] + go;
            cst = sigm(xf)*cst + sigm(xi)*tanhf(xg);
            float hv = sigm(xo)*tanhf(cst);
            __stcg(g_hbuf + ub*EMB + c0 + uj, hv);
            g_rnn[(size_t)t*(NB*EMB) + ub*EMB + c0 + uj] = hv;
        }
        __syncthreads();
        if (tid == 0){
            __threadfence();
            atomicAdd(&g_bar, 1);
            int target = 128*(t+1);
            while (*((volatile int*)&g_bar) < target) {}
            __threadfence();
        }
        __syncthreads();
    }
}

// ---------------- host launch ----------------
#define GEMM_SMEM 122880

extern "C" void kernel_launch(void* const* d_in, const int* in_sizes, int n_in,
                              void* d_out, int out_size){
    const float* inputs   = (const float*)d_in[0];
    const float* Wih      = (const float*)d_in[3];
    const float* Whh      = (const float*)d_in[4];
    const float* bih      = (const float*)d_in[5];
    const float* bhh      = (const float*)d_in[6];
    const float* lnstart_g=(const float*)d_in[7],  *lnstart_b=(const float*)d_in[8];
    const float* lnmem_g  =(const float*)d_in[9],  *lnmem_b  =(const float*)d_in[10];
    const float* lnmid_g  =(const float*)d_in[11], *lnmid_b  =(const float*)d_in[12];
    const float* lnff_g   =(const float*)d_in[13], *lnff_b   =(const float*)d_in[14];
    const float* lnxff_g  =(const float*)d_in[15], *lnxff_b  =(const float*)d_in[16];
    const float* qln_g    =(const float*)d_in[17], *qln_b    =(const float*)d_in[18];
    const float* qs       =(const float*)d_in[19], *ksp      =(const float*)d_in[20];
    const float* vsp      =(const float*)d_in[21];
    const float* opW      =(const float*)d_in[22], *opb      =(const float*)d_in[23];
    const float* qlW      =(const float*)d_in[24], *qlb      =(const float*)d_in[25];
    const float* boomW    =(const float*)d_in[26], *boomb    =(const float*)d_in[27];
    float* out = (float*)d_out;

    cudaFuncSetAttribute(gemm_kernel, cudaFuncAttributeMaxDynamicSharedMemorySize, GEMM_SMEM);
    cudaFuncSetAttribute(lstm_kernel, cudaFuncAttributeMaxDynamicSharedMemorySize, LSTM_SMEM);

    float *p_G,*p_rnn,*p_hmid,*p_vsc,*p_qpre,*p_scores,*p_h2,*p_res,*p_bias4,*p_qsg,*p_ksg,*p_vsg;
    bf16 *p_xlnh,*p_xlnl,*p_Wihh,*p_Wihl,*p_hmidh,*p_hmidl,*p_qsch,*p_qscl,*p_ksch,*p_kscl;
    bf16 *p_xffh,*p_xffl,*p_vTh,*p_vTl,*p_wh,*p_wl,*p_qlWh,*p_qlWl,*p_bmWh,*p_bmWl;
    cudaGetSymbolAddress((void**)&p_G, g_G);
    cudaGetSymbolAddress((void**)&p_rnn, g_rnn);
    cudaGetSymbolAddress((void**)&p_hmid, g_hmid);
    cudaGetSymbolAddress((void**)&p_vsc, g_vsc);
    cudaGetSymbolAddress((void**)&p_qpre, g_qpre);
    cudaGetSymbolAddress((void**)&p_scores, g_scores);
    cudaGetSymbolAddress((void**)&p_h2, g_h2);
    cudaGetSymbolAddress((void**)&p_res, g_res);
    cudaGetSymbolAddress((void**)&p_bias4, g_bias4);
    cudaGetSymbolAddress((void**)&p_qsg, g_qsg);
    cudaGetSymbolAddress((void**)&p_ksg, g_ksg);
    cudaGetSymbolAddress((void**)&p_vsg, g_vsg);
    cudaGetSymbolAddress((void**)&p_xlnh, g_xlnh);  cudaGetSymbolAddress((void**)&p_xlnl, g_xlnl);
    cudaGetSymbolAddress((void**)&p_Wihh, g_Wihh);  cudaGetSymbolAddress((void**)&p_Wihl, g_Wihl);
    cudaGetSymbolAddress((void**)&p_hmidh, g_hmidh);cudaGetSymbolAddress((void**)&p_hmidl, g_hmidl);
    cudaGetSymbolAddress((void**)&p_qsch, g_qsch);  cudaGetSymbolAddress((void**)&p_qscl, g_qscl);
    cudaGetSymbolAddress((void**)&p_ksch, g_ksch);  cudaGetSymbolAddress((void**)&p_kscl, g_kscl);
    cudaGetSymbolAddress((void**)&p_xffh, g_xffh);  cudaGetSymbolAddress((void**)&p_xffl, g_xffl);
    cudaGetSymbolAddress((void**)&p_vTh, g_vTh);    cudaGetSymbolAddress((void**)&p_vTl, g_vTl);
    cudaGetSymbolAddress((void**)&p_wh, g_wh);      cudaGetSymbolAddress((void**)&p_wl, g_wl);
    cudaGetSymbolAddress((void**)&p_qlWh, g_qlWh);  cudaGetSymbolAddress((void**)&p_qlWl, g_qlWl);
    cudaGetSymbolAddress((void**)&p_bmWh, g_bmWh);  cudaGetSymbolAddress((void**)&p_bmWl, g_bmWl);

    prep_kernel<<<16,256>>>(bih, bhh, qs, ksp);
    op_gemm_kernel<<<8,256>>>(vsp, opW, opb);
    vsg_kernel<<<4,256>>>();
    split_kernel<<<(G4*EMB)/256,256>>>(Wih, p_Wihh, p_Wihl, G4*EMB);
    split_kernel<<<(EMB*EMB)/256,256>>>(qlW, p_qlWh, p_qlWl, EMB*EMB);
    split_kernel<<<(EMB*EMB)/256,256>>>(boomW, p_bmWh, p_bmWl, EMB*EMB);

    // ln(inputs) -> xln pair
    ln_kernel<<<RTOT,256>>>(inputs,
        nullptr, p_xlnh, p_xlnl, lnstart_g, lnstart_b, nullptr,
        nullptr, nullptr, nullptr, nullptr, nullptr, nullptr,
        nullptr, nullptr, nullptr, nullptr, nullptr, nullptr);
    // G = xln @ Wih^T + (bih+bhh)
    gemm_kernel<<<dim3(32,64,1),256,GEMM_SMEM>>>(p_xlnh,p_xlnl,EMB,0, p_Wihh,p_Wihl,EMB,0,
        p_G,G4,0, RTOT,G4,EMB, p_bias4, nullptr,0,0, 1.f, 0);
    // LSTM recurrence
    lstm_kernel<<<128,256,LSTM_SMEM>>>(Whh);
    // ln(rnn) -> hmid (f32+pair), ksc pair (*ksg), vsc f32 (*vsg)
    ln_kernel<<<RTOT,256>>>(p_rnn,
        p_hmid, p_hmidh, p_hmidl, lnmid_g, lnmid_b, nullptr,
        nullptr, p_ksch, p_kscl, lnmem_g, lnmem_b, p_ksg,
        p_vsc, nullptr, nullptr, lnmem_g, lnmem_b, p_vsg);
    // qpre = hmid @ qlW^T + qlb
    gemm_kernel<<<dim3(8,64,1),256,GEMM_SMEM>>>(p_hmidh,p_hmidl,EMB,0, p_qlWh,p_qlWl,EMB,0,
        p_qpre,EMB,0, RTOT,EMB,EMB, qlb, nullptr,0,0, 1.f, 0);
    // ln(qpre) -> qsc pair (*qsg)
    ln_kernel<<<RTOT,256>>>(p_qpre,
        nullptr, p_qsch, p_qscl, qln_g, qln_b, p_qsg,
        nullptr, nullptr, nullptr, nullptr, nullptr, nullptr,
        nullptr, nullptr, nullptr, nullptr, nullptr, nullptr);
    // scores[b] = qsc @ ksc^T / 32 (causal tile skip)
    gemm_kernel<<<dim3(16,8,8),256,GEMM_SMEM>>>(p_qsch,p_qscl,NB*EMB,EMB, p_ksch,p_kscl,NB*EMB,EMB,
        p_scores,SQ,(long long)SQ*SQ, SQ,SQ,EMB, nullptr, nullptr,0,0, 0.03125f, GF_CSKIP);
    // softmax -> w pair
    softmax_kernel<<<RTOT,256>>>(p_scores, p_wh, p_wl);
    // v transpose
    transpose_v<<<dim3(32,64,8),dim3(32,8)>>>(p_vsc, p_vTh, p_vTl);
    // h2 = w @ vT^T + hmid (causal K clamp)
    gemm_kernel<<<dim3(8,8,8),256,GEMM_SMEM>>>(p_wh,p_wl,SQ,(long long)SQ*SQ, p_vTh,p_vTl,SQ,(long long)EMB*SQ,
        p_h2,NB*EMB,EMB, SQ,EMB,SQ, nullptr, p_hmid,NB*EMB,EMB, 1.f, GF_KCLAMP);
    // ln(h2) -> xff pair, res f32
    ln_kernel<<<RTOT,256>>>(p_h2,
        nullptr, p_xffh, p_xffl, lnxff_g, lnxff_b, nullptr,
        p_res, nullptr, nullptr, lnff_g, lnff_b, nullptr,
        nullptr, nullptr, nullptr, nullptr, nullptr, nullptr);
    // out = gelu(xff @ boomW^T + boomb) + res
    gemm_kernel<<<dim3(8,64,1),256,GEMM_SMEM>>>(p_xffh,p_xffl,EMB,0, p_bmWh,p_bmWl,EMB,0,
        out,EMB,0, RTOT,EMB,EMB, boomb, p_res,EMB,0, 1.f, GF_GELU);
}

// round 13
// speedup vs baseline: 1.5590x; 1.5590x over previous
#include <cuda_runtime.h>
#include <cuda_bf16.h>
#include <mma.h>
#include <cstdint>

using namespace nvcuda;

#define SQ 2048
#define NB 8
#define EMB 1024
#define RTOT (SQ*NB)
#define G4 (4*EMB)

#define GF_GELU   1
#define GF_CSKIP  2
#define GF_KCLAMP 4

typedef __nv_bfloat16 bf16;

// ---------------- device scratch (static; no allocation allowed) ----------------
__device__ float g_G    [(size_t)RTOT*G4];
__device__ float g_rnn  [(size_t)RTOT*EMB];
__device__ float g_hmid [(size_t)RTOT*EMB];
__device__ float g_vsc  [(size_t)RTOT*EMB];
__device__ float g_qpre [(size_t)RTOT*EMB];
__device__ float g_scores[(size_t)NB*SQ*SQ];
__device__ float g_h2   [(size_t)RTOT*EMB];
__device__ float g_res  [(size_t)RTOT*EMB];
__device__ float g_bias4[G4];
__device__ float g_op   [2*EMB];
__device__ float g_qsg  [EMB];
__device__ float g_ksg  [EMB];
__device__ float g_vsg  [EMB];
__device__ float g_hbuf [NB*EMB];
__device__ int   g_bar;

__device__ __align__(256) bf16 g_xlnh [(size_t)RTOT*EMB];
__device__ __align__(256) bf16 g_xlnl [(size_t)RTOT*EMB];
__device__ __align__(256) bf16 g_Wihh [(size_t)G4*EMB];
__device__ __align__(256) bf16 g_Wihl [(size_t)G4*EMB];
__device__ __align__(256) bf16 g_hmidh[(size_t)RTOT*EMB];
__device__ __align__(256) bf16 g_hmidl[(size_t)RTOT*EMB];
__device__ __align__(256) bf16 g_qsch [(size_t)RTOT*EMB];
__device__ __align__(256) bf16 g_qscl [(size_t)RTOT*EMB];
__device__ __align__(256) bf16 g_ksch [(size_t)RTOT*EMB];
__device__ __align__(256) bf16 g_kscl [(size_t)RTOT*EMB];
__device__ __align__(256) bf16 g_xffh [(size_t)RTOT*EMB];
__device__ __align__(256) bf16 g_xffl [(size_t)RTOT*EMB];
__device__ __align__(256) bf16 g_vTh  [(size_t)NB*EMB*SQ];
__device__ __align__(256) bf16 g_vTl  [(size_t)NB*EMB*SQ];
__device__ __align__(256) bf16 g_wh   [(size_t)NB*SQ*SQ];
__device__ __align__(256) bf16 g_wl   [(size_t)NB*SQ*SQ];
__device__ __align__(256) bf16 g_qlWh [(size_t)EMB*EMB];
__device__ __align__(256) bf16 g_qlWl [(size_t)EMB*EMB];
__device__ __align__(256) bf16 g_bmWh [(size_t)EMB*EMB];
__device__ __align__(256) bf16 g_bmWl [(size_t)EMB*EMB];

__device__ __forceinline__ float sigm(float x){ return 1.0f/(1.0f + expf(-x)); }

// ---------------- prep ----------------
__global__ void prep_kernel(const float* __restrict__ bih, const float* __restrict__ bhh,
                            const float* __restrict__ qs, const float* __restrict__ ksp){
    int i = blockIdx.x*256 + threadIdx.x;
    if (i < G4) g_bias4[i] = bih[i] + bhh[i];
    if (i < EMB){
        g_qsg[i] = sigm(qs[i]); g_ksg[i] = sigm(ksp[i]);
        #pragma unroll
        for (int b = 0; b < NB; b++) g_hbuf[i + b*EMB] = 0.f;
    }
    if (i == 0) g_bar = 0;
}

__global__ void op_gemm_kernel(const float* __restrict__ vsp, const float* __restrict__ opW,
                               const float* __restrict__ opb){
    __shared__ float vo[EMB];
    int tid = threadIdx.x;
    for (int i = tid; i < EMB; i += 256) vo[i] = sigm(vsp[i]);
    __syncthreads();
    int j = blockIdx.x*256 + tid;
    float acc = 0.f;
    const float* w = opW + (size_t)j*EMB;
    for (int e = 0; e < EMB; e += 4){
        float4 wv = *(const float4*)(w + e);
        acc += wv.x*vo[e] + wv.y*vo[e+1] + wv.z*vo[e+2] + wv.w*vo[e+3];
    }
    g_op[j] = acc + opb[j];
}

__global__ void vsg_kernel(){
    int i = blockIdx.x*256 + threadIdx.x;
    if (i < EMB) g_vsg[i] = sigm(g_op[EMB + i]) * tanhf(g_op[i]);
}

// fp32 -> bf16 hi/lo split
__global__ void split_kernel(const float* __restrict__ src, bf16* __restrict__ hi,
                             bf16* __restrict__ lo, int n){
    int i = blockIdx.x*256 + threadIdx.x;
    if (i < n){
        float v = src[i];
        bf16 h = __float2bfloat16(v);
        hi[i] = h; lo[i] = __float2bfloat16(v - __bfloat162float(h));
    }
}

// ---------------- block reductions ----------------
__device__ __forceinline__ float bsum(float v, float* buf){
    #pragma unroll
    for (int o = 16; o; o >>= 1) v += __shfl_xor_sync(0xffffffffu, v, o);
    int w = threadIdx.x >> 5;
    if ((threadIdx.x & 31) == 0) buf[w] = v;
    __syncthreads();
    if (threadIdx.x == 0){ float s = 0.f; for (int i = 0; i < 8; i++) s += buf[i]; buf[0] = s; }
    __syncthreads();
    float r = buf[0]; __syncthreads();
    return r;
}
__device__ __forceinline__ float bmax(float v, float* buf){
    #pragma unroll
    for (int o = 16; o; o >>= 1) v = fmaxf(v, __shfl_xor_sync(0xffffffffu, v, o));
    int w = threadIdx.x >> 5;
    if ((threadIdx.x & 31) == 0) buf[w] = v;
    __syncthreads();
    if (threadIdx.x == 0){ float s = buf[0]; for (int i = 1; i < 8; i++) s = fmaxf(s, buf[i]); buf[0] = s; }
    __syncthreads();
    float r = buf[0]; __syncthreads();
    return r;
}

// ---------------- layer norm: 3 outputs share stats; each may emit f32 and/or bf16 pair ----------------
__global__ void __launch_bounds__(256) ln_kernel(const float* __restrict__ in,
    float* f1, bf16* h1, bf16* l1, const float* g1, const float* b1, const float* s1,
    float* f2, bf16* h2, bf16* l2, const float* g2, const float* b2, const float* s2,
    float* f3, bf16* h3, bf16* l3, const float* g3, const float* b3, const float* s3){
    __shared__ float buf[8];
    size_t row = blockIdx.x;
    int tid = threadIdx.x, e = tid*4;
    float4 x = *(const float4*)(in + row*EMB + e);
    float m = bsum(x.x + x.y + x.z + x.w, buf) * (1.f/EMB);
    float d0 = x.x - m, d1 = x.y - m, d2 = x.z - m, d3 = x.w - m;
    float v = bsum(d0*d0 + d1*d1 + d2*d2 + d3*d3, buf) * (1.f/EMB);
    float rstd = rsqrtf(v + 1e-12f);
    #define EMIT(f,h,l,g,b,s) if (g){ \
        float4 gv = *(const float4*)((g)+e); float4 bv = *(const float4*)((b)+e); \
        float4 y; y.x = d0*rstd*gv.x + bv.x; y.y = d1*rstd*gv.y + bv.y; \
        y.z = d2*rstd*gv.z + bv.z; y.w = d3*rstd*gv.w + bv.w; \
        if (s){ float4 sv = *(const float4*)((s)+e); y.x*=sv.x; y.y*=sv.y; y.z*=sv.z; y.w*=sv.w; } \
        if (f) *(float4*)((f) + row*EMB + e) = y; \
        if (h){ bf16 p0=__float2bfloat16(y.x), p1=__float2bfloat16(y.y); \
                bf16 p2=__float2bfloat16(y.z), p3=__float2bfloat16(y.w); \
                *(__nv_bfloat162*)((h)+row*EMB+e)   = __halves2bfloat162(p0,p1); \
                *(__nv_bfloat162*)((h)+row*EMB+e+2) = __halves2bfloat162(p2,p3); \
                *(__nv_bfloat162*)((l)+row*EMB+e)   = __halves2bfloat162( \
                    __float2bfloat16(y.x-__bfloat162float(p0)), __float2bfloat16(y.y-__bfloat162float(p1))); \
                *(__nv_bfloat162*)((l)+row*EMB+e+2) = __halves2bfloat162( \
                    __float2bfloat16(y.z-__bfloat162float(p2)), __float2bfloat16(y.w-__bfloat162float(p3))); } }
    EMIT(f1,h1,l1,g1,b1,s1); EMIT(f2,h2,l2,g2,b2,s2); EMIT(f3,h3,l3,g3,b3,s3);
    #undef EMIT
}

// ---------------- causal softmax -> bf16 pair, zero-fill to 128 boundary ----------------
__global__ void __launch_bounds__(256) softmax_kernel(const float* __restrict__ sc,
        bf16* __restrict__ whi, bf16* __restrict__ wlo){
    __shared__ float buf[8];
    int blk = blockIdx.x;
    int s = blk & (SQ-1);
    const float* row = sc + (size_t)blk*SQ;
    int n = s + 1;
    int fill = ((s >> 7) + 1) << 7;
    float vals[8];
    float mx = -1e30f;
    int cnt = 0;
    for (int k = threadIdx.x; k < n; k += 256){ float v = row[k]; vals[cnt++] = v; mx = fmaxf(mx, v); }
    mx = bmax(mx, buf);
    float sm = 0.f;
    for (int i = 0; i < cnt; i++){ float e = expf(vals[i] - mx); vals[i] = e; sm += e; }
    sm = bsum(sm, buf);
    float inv = 1.f/sm;
    bf16* wh = whi + (size_t)blk*SQ;
    bf16* wl = wlo + (size_t)blk*SQ;
    cnt = 0;
    for (int k = threadIdx.x; k < fill; k += 256){
        float v = (k < n) ? vals[cnt++]*inv : 0.f;
        bf16 h = __float2bfloat16(v);
        wh[k] = h; wl[k] = __float2bfloat16(v - __bfloat162float(h));
    }
}

// ---------------- v transpose: [s][b][e] f32 -> [b][e][s] bf16 pair ----------------
__global__ void transpose_v(const float* __restrict__ vsc, bf16* __restrict__ vTh,
                            bf16* __restrict__ vTl){
    __shared__ float t[32][33];
    int b = blockIdx.z;
    int e0 = blockIdx.x*32, s0 = blockIdx.y*32;
    int x = threadIdx.x, y0 = threadIdx.y;
    for (int yy = y0; yy < 32; yy += 8)
        t[yy][x] = vsc[((size_t)(s0+yy)*NB + b)*EMB + e0 + x];
    __syncthreads();
    for (int yy = y0; yy < 32; yy += 8){
        float v = t[x][yy];
        size_t o = (size_t)b*EMB*SQ + (size_t)(e0+yy)*SQ + s0 + x;
        bf16 h = __float2bfloat16(v);
        vTh[o] = h; vTl[o] = __float2bfloat16(v - __bfloat162float(h));
    }
}

// ---------------- split-bf16 GEMM: C = alpha*(A@B^T)[+bias][gelu][+add] ----------------
// block tile 128x64x32, 8 warps of 32x32, 3-stage cp.async, 2 CTAs/SM
__device__ __forceinline__ void cpa16(bf16* dst, const bf16* src){
    uint32_t d = (uint32_t)__cvta_generic_to_shared(dst);
    asm volatile("cp.async.cg.shared.global [%0], [%1], 16;" :: "r"(d), "l"(src));
}

// smem (bf16 units): ASh @0 (3 x 5120), ASl @15360, BSh @30720 (3 x 2560), BSl @38400
// total 46080 bf16 = 92160 B
#define GEMM_SMEM 92160

__global__ void __launch_bounds__(256,2) gemm_kernel(
    const bf16* __restrict__ Ah, const bf16* __restrict__ Al, long long lda, long long sAz,
    const bf16* __restrict__ Bh, const bf16* __restrict__ Bl, long long ldb, long long sBz,
    float* __restrict__ C, long long ldc, long long sCz,
    int M, int N, int K,
    const float* __restrict__ bias, const float* __restrict__ addp,
    long long ldadd, long long sAddz, float alpha, int flags){
    extern __shared__ bf16 sm[];
    int m0 = blockIdx.y*128, n0 = blockIdx.x*64;
    if ((flags & GF_CSKIP) && n0 > m0 + 127) return;
    int Keff = (flags & GF_KCLAMP) ? min(K, m0 + 128) : K;
    int nkt = Keff >> 5;

    Ah += (size_t)blockIdx.z*sAz; Al += (size_t)blockIdx.z*sAz;
    Bh += (size_t)blockIdx.z*sBz; Bl += (size_t)blockIdx.z*sBz;
    C  += (size_t)blockIdx.z*sCz;
    if (addp) addp += (size_t)blockIdx.z*sAddz;

    int tid = threadIdx.x, warpId = tid >> 5, lane = tid & 31;
    int wm = warpId >> 1, wn = warpId & 1;

    wmma::fragment<wmma::accumulator,16,16,16,float> acc[2][2];
    #pragma unroll
    for (int i=0;i<2;i++)
        #pragma unroll
        for (int j=0;j<2;j++) wmma::fill_fragment(acc[i][j], 0.f);

    auto loadg = [&](int kt){
        int k0 = kt << 5, s = kt % 3;
        bf16* ash = sm + s*5120;
        bf16* asl = sm + 15360 + s*5120;
        bf16* bsh = sm + 30720 + s*2560;
        bf16* bsl = sm + 38400 + s*2560;
        #pragma unroll
        for (int i=0;i<2;i++){ int id = tid + i*256; int r = id>>2, c = (id&3)*8;
            cpa16(ash + r*40 + c, Ah + (size_t)(m0+r)*lda + k0 + c);
            cpa16(asl + r*40 + c, Al + (size_t)(m0+r)*lda + k0 + c); }
        { int r = tid>>2, c = (tid&3)*8;
            cpa16(bsh + r*40 + c, Bh + (size_t)(n0+r)*ldb + k0 + c);
            cpa16(bsl + r*40 + c, Bl + (size_t)(n0+r)*ldb + k0 + c); }
        asm volatile("cp.async.commit_group;");
    };

    loadg(0);
    if (nkt > 1) loadg(1);
    for (int kt = 0; kt < nkt; ++kt){
        if (kt == nkt-1) asm volatile("cp.async.wait_group 0;");
        else             asm volatile("cp.async.wait_group 1;");
        __syncthreads();
        if (kt + 2 < nkt) loadg(kt+2);
        int s = kt % 3;
        const bf16* ash = sm + s*5120;
        const bf16* asl = sm + 15360 + s*5120;
        const bf16* bsh = sm + 30720 + s*2560;
        const bf16* bsl = sm + 38400 + s*2560;
        #pragma unroll
        for (int ks = 0; ks < 2; ++ks){
            wmma::fragment<wmma::matrix_a,16,16,16,bf16,wmma::row_major> ah[2], al[2];
            wmma::fragment<wmma::matrix_b,16,16,16,bf16,wmma::col_major> bh[2], bl[2];
            #pragma unroll
            for (int im=0;im<2;im++){
                const bf16* p = ash + (wm*32+im*16)*40 + ks*16;
                wmma::load_matrix_sync(ah[im], p, 40);
                wmma::load_matrix_sync(al[im], asl + (wm*32+im*16)*40 + ks*16, 40);
            }
            #pragma unroll
            for (int in=0;in<2;in++){
                wmma::load_matrix_sync(bh[in], bsh + (wn*32+in*16)*40 + ks*16, 40);
                wmma::load_matrix_sync(bl[in], bsl + (wn*32+in*16)*40 + ks*16, 40);
            }
            #pragma unroll
            for (int im=0;im<2;im++)
                #pragma unroll
                for (int in=0;in<2;in++){
                    wmma::mma_sync(acc[im][in], ah[im], bh[in], acc[im][in]);
                    wmma::mma_sync(acc[im][in], ah[im], bl[in], acc[im][in]);
                    wmma::mma_sync(acc[im][in], al[im], bh[in], acc[im][in]);
                }
        }
        __syncthreads();
    }

    // epilogue: per-warp 32x32 staged in smem
    float* stg = (float*)sm + warpId*(32*36);
    #pragma unroll
    for (int im=0;im<2;im++)
        #pragma unroll
        for (int in=0;in<2;in++)
            wmma::store_matrix_sync(stg + im*16*36 + in*16, acc[im][in], 36, wmma::mem_row_major);
    __syncwarp();
    #pragma unroll 4
    for (int i = 0; i < 32; i++){
        float v = stg[i*36 + lane] * alpha;
        int grow = m0 + wm*32 + i, gcol = n0 + wn*32 + lane;
        if (bias) v += __ldg(bias + gcol);
        if (flags & GF_GELU) v = v * (1.f/(1.f + expf(-1.702f*v)));
        if (addp) v += addp[(size_t)grow*ldadd + gcol];
        C[(size_t)grow*ldc + gcol] = v;
    }
}

// ---------------- persistent LSTM: 128 blocks x 256 threads ----------------
union __align__(16) F4U { float4 f; unsigned long long u[2]; };
union U64F2 { unsigned long long u; float2 f; };
__device__ __forceinline__ void ffma2(unsigned long long& acc, unsigned long long a, unsigned long long b){
    asm("fma.rn.f32x2 %0, %1, %2, %0;" : "+l"(acc) : "l"(a), "l"(b));
}

#define WSTR 1044
#define HSTR 1036
#define LSTM_SMEM ((32*WSTR + 8*HSTR + 256)*4)

__global__ void __launch_bounds__(256,1) lstm_kernel(const float* __restrict__ Whh){
    extern __shared__ float smf[];
    float* wsm = smf;
    float* hsm = smf + 32*WSTR;
    float* red = hsm + 8*HSTR;

    int tid = threadIdx.x;
    int c0 = blockIdx.x*8;
    int r = tid >> 3, b = tid & 7;

    for (int idx = tid; idx < 32*256; idx += 256){
        int rr = idx >> 8, k4 = idx & 255;
        int gate = rr >> 3, j = rr & 7;
        *(float4*)(wsm + rr*WSTR + k4*4) =
            *(const float4*)(Whh + ((size_t)(gate*1024 + c0 + j))*1024 + k4*4);
    }

    float cst = 0.f;
    int uj = tid >> 3, ub = tid & 7;

    const float* wp = wsm + r*WSTR;
    const float* hp = hsm + b*HSTR;

    for (int t = 0; t < SQ; ++t){
        float gi=0.f, gf=0.f, gg=0.f, go=0.f;
        if (tid < 64){
            const float* Gp = g_G + ((size_t)t*NB + ub)*G4 + c0 + uj;
            gi = __ldcs(Gp); gf = __ldcs(Gp+1024); gg = __ldcs(Gp+2048); go = __ldcs(Gp+3072);
        }
        for (int idx = tid; idx < 2048; idx += 256){
            int hb = idx >> 8, k4 = idx & 255;
            float4 hv = __ldcg((const float4*)(g_hbuf + hb*EMB + k4*4));
            *(float4*)(hsm + hb*HSTR + k4*4) = hv;
        }
        __syncthreads();

        U64F2 acc; acc.f = make_float2(0.f, 0.f);
        #pragma unroll 4
        for (int k = 0; k < 1024; k += 4){
            F4U wv = *(const F4U*)(wp + k);
            F4U hv = *(const F4U*)(hp + k);
            ffma2(acc.u, wv.u[0], hv.u[0]);
            ffma2(acc.u, wv.u[1], hv.u[1]);
        }
        red[r*8 + b] = acc.f.x + acc.f.y;
        __syncthreads();

        if (tid < 64){
            float xi = red[(uj     )*8 + ub] + gi;
            float xf = red[(8 + uj )*8 + ub] + gf;
            float xg = red[(16 + uj)*8 + ub] + gg;
            float xo = red[(24 + uj)*8 + ub] + go;
            cst = sigm(xf)*cst + sigm(xi)*tanhf(xg);
            float hv = sigm(xo)*tanhf(cst);
            __stcg(g_hbuf + ub*EMB + c0 + uj, hv);
            g_rnn[(size_t)t*(NB*EMB) + ub*EMB + c0 + uj] = hv;
        }
        __syncthreads();
        if (tid == 0){
            __threadfence();
            atomicAdd(&g_bar, 1);
            int target = 128*(t+1);
            while (*((volatile int*)&g_bar) < target) {}
            __threadfence();
        }
        __syncthreads();
    }
}

// ---------------- host launch ----------------
extern "C" void kernel_launch(void* const* d_in, const int* in_sizes, int n_in,
                              void* d_out, int out_size){
    const float* inputs   = (const float*)d_in[0];
    const float* Wih      = (const float*)d_in[3];
    const float* Whh      = (const float*)d_in[4];
    const float* bih      = (const float*)d_in[5];
    const float* bhh      = (const float*)d_in[6];
    const float* lnstart_g=(const float*)d_in[7],  *lnstart_b=(const float*)d_in[8];
    const float* lnmem_g  =(const float*)d_in[9],  *lnmem_b  =(const float*)d_in[10];
    const float* lnmid_g  =(const float*)d_in[11], *lnmid_b  =(const float*)d_in[12];
    const float* lnff_g   =(const float*)d_in[13], *lnff_b   =(const float*)d_in[14];
    const float* lnxff_g  =(const float*)d_in[15], *lnxff_b  =(const float*)d_in[16];
    const float* qln_g    =(const float*)d_in[17], *qln_b    =(const float*)d_in[18];
    const float* qs       =(const float*)d_in[19], *ksp      =(const float*)d_in[20];
    const float* vsp      =(const float*)d_in[21];
    const float* opW      =(const float*)d_in[22], *opb      =(const float*)d_in[23];
    const float* qlW      =(const float*)d_in[24], *qlb      =(const float*)d_in[25];
    const float* boomW    =(const float*)d_in[26], *boomb    =(const float*)d_in[27];
    float* out = (float*)d_out;

    cudaFuncSetAttribute(gemm_kernel, cudaFuncAttributeMaxDynamicSharedMemorySize, GEMM_SMEM);
    cudaFuncSetAttribute(lstm_kernel, cudaFuncAttributeMaxDynamicSharedMemorySize, LSTM_SMEM);

    float *p_G,*p_rnn,*p_hmid,*p_vsc,*p_qpre,*p_scores,*p_h2,*p_res,*p_bias4,*p_qsg,*p_ksg,*p_vsg;
    bf16 *p_xlnh,*p_xlnl,*p_Wihh,*p_Wihl,*p_hmidh,*p_hmidl,*p_qsch,*p_qscl,*p_ksch,*p_kscl;
    bf16 *p_xffh,*p_xffl,*p_vTh,*p_vTl,*p_wh,*p_wl,*p_qlWh,*p_qlWl,*p_bmWh,*p_bmWl;
    cudaGetSymbolAddress((void**)&p_G, g_G);
    cudaGetSymbolAddress((void**)&p_rnn, g_rnn);
    cudaGetSymbolAddress((void**)&p_hmid, g_hmid);
    cudaGetSymbolAddress((void**)&p_vsc, g_vsc);
    cudaGetSymbolAddress((void**)&p_qpre, g_qpre);
    cudaGetSymbolAddress((void**)&p_scores, g_scores);
    cudaGetSymbolAddress((void**)&p_h2, g_h2);
    cudaGetSymbolAddress((void**)&p_res, g_res);
    cudaGetSymbolAddress((void**)&p_bias4, g_bias4);
    cudaGetSymbolAddress((void**)&p_qsg, g_qsg);
    cudaGetSymbolAddress((void**)&p_ksg, g_ksg);
    cudaGetSymbolAddress((void**)&p_vsg, g_vsg);
    cudaGetSymbolAddress((void**)&p_xlnh, g_xlnh);  cudaGetSymbolAddress((void**)&p_xlnl, g_xlnl);
    cudaGetSymbolAddress((void**)&p_Wihh, g_Wihh);  cudaGetSymbolAddress((void**)&p_Wihl, g_Wihl);
    cudaGetSymbolAddress((void**)&p_hmidh, g_hmidh);cudaGetSymbolAddress((void**)&p_hmidl, g_hmidl);
    cudaGetSymbolAddress((void**)&p_qsch, g_qsch);  cudaGetSymbolAddress((void**)&p_qscl, g_qscl);
    cudaGetSymbolAddress((void**)&p_ksch, g_ksch);  cudaGetSymbolAddress((void**)&p_kscl, g_kscl);
    cudaGetSymbolAddress((void**)&p_xffh, g_xffh);  cudaGetSymbolAddress((void**)&p_xffl, g_xffl);
    cudaGetSymbolAddress((void**)&p_vTh, g_vTh);    cudaGetSymbolAddress((void**)&p_vTl, g_vTl);
    cudaGetSymbolAddress((void**)&p_wh, g_wh);      cudaGetSymbolAddress((void**)&p_wl, g_wl);
    cudaGetSymbolAddress((void**)&p_qlWh, g_qlWh);  cudaGetSymbolAddress((void**)&p_qlWl, g_qlWl);
    cudaGetSymbolAddress((void**)&p_bmWh, g_bmWh);  cudaGetSymbolAddress((void**)&p_bmWl, g_bmWl);

    prep_kernel<<<16,256>>>(bih, bhh, qs, ksp);
    op_gemm_kernel<<<8,256>>>(vsp, opW, opb);
    vsg_kernel<<<4,256>>>();
    split_kernel<<<(G4*EMB)/256,256>>>(Wih, p_Wihh, p_Wihl, G4*EMB);
    split_kernel<<<(EMB*EMB)/256,256>>>(qlW, p_qlWh, p_qlWl, EMB*EMB);
    split_kernel<<<(EMB*EMB)/256,256>>>(boomW, p_bmWh, p_bmWl, EMB*EMB);

    // ln(inputs) -> xln pair
    ln_kernel<<<RTOT,256>>>(inputs,
        nullptr, p_xlnh, p_xlnl, lnstart_g, lnstart_b, nullptr,
        nullptr, nullptr, nullptr, nullptr, nullptr, nullptr,
        nullptr, nullptr, nullptr, nullptr, nullptr, nullptr);
    // G = xln @ Wih^T + (bih+bhh)
    gemm_kernel<<<dim3(64,128,1),256,GEMM_SMEM>>>(p_xlnh,p_xlnl,EMB,0, p_Wihh,p_Wihl,EMB,0,
        p_G,G4,0, RTOT,G4,EMB, p_bias4, nullptr,0,0, 1.f, 0);
    // LSTM recurrence
    lstm_kernel<<<128,256,LSTM_SMEM>>>(Whh);
    // ln(rnn) -> hmid (f32+pair), ksc pair (*ksg), vsc f32 (*vsg)
    ln_kernel<<<RTOT,256>>>(p_rnn,
        p_hmid, p_hmidh, p_hmidl, lnmid_g, lnmid_b, nullptr,
        nullptr, p_ksch, p_kscl, lnmem_g, lnmem_b, p_ksg,
        p_vsc, nullptr, nullptr, lnmem_g, lnmem_b, p_vsg);
    // qpre = hmid @ qlW^T + qlb
    gemm_kernel<<<dim3(16,128,1),256,GEMM_SMEM>>>(p_hmidh,p_hmidl,EMB,0, p_qlWh,p_qlWl,EMB,0,
        p_qpre,EMB,0, RTOT,EMB,EMB, qlb, nullptr,0,0, 1.f, 0);
    // ln(qpre) -> qsc pair (*qsg)
    ln_kernel<<<RTOT,256>>>(p_qpre,
        nullptr, p_qsch, p_qscl, qln_g, qln_b, p_qsg,
        nullptr, nullptr, nullptr, nullptr, nullptr, nullptr,
        nullptr, nullptr, nullptr, nullptr, nullptr, nullptr);
    // scores[b] = qsc @ ksc^T / 32 (causal tile skip)
    gemm_kernel<<<dim3(32,16,8),256,GEMM_SMEM>>>(p_qsch,p_qscl,NB*EMB,EMB, p_ksch,p_kscl,NB*EMB,EMB,
        p_scores,SQ,(long long)SQ*SQ, SQ,SQ,EMB, nullptr, nullptr,0,0, 0.03125f, GF_CSKIP);
    // softmax -> w pair
    softmax_kernel<<<RTOT,256>>>(p_scores, p_wh, p_wl);
    // v transpose
    transpose_v<<<dim3(32,64,8),dim3(32,8)>>>(p_vsc, p_vTh, p_vTl);
    // h2 = w @ vT^T + hmid (causal K clamp)
    gemm_kernel<<<dim3(16,16,8),256,GEMM_SMEM>>>(p_wh,p_wl,SQ,(long long)SQ*SQ, p_vTh,p_vTl,SQ,(long long)EMB*SQ,
        p_h2,NB*EMB,EMB, SQ,EMB,SQ, nullptr, p_hmid,NB*EMB,EMB, 1.f, GF_KCLAMP);
    // ln(h2) -> xff pair, res f32
    ln_kernel<<<RTOT,256>>>(p_h2,
        nullptr, p_xffh, p_xffl, lnxff_g, lnxff_b, nullptr,
        p_res, nullptr, nullptr, lnff_g, lnff_b, nullptr,
        nullptr, nullptr, nullptr, nullptr, nullptr, nullptr);
    // out = gelu(xff @ boomW^T + boomb) + res
    gemm_kernel<<<dim3(16,128,1),256,GEMM_SMEM>>>(p_xffh,p_xffl,EMB,0, p_bmWh,p_bmWl,EMB,0,
        out,EMB,0, RTOT,EMB,EMB, boomb, p_res,EMB,0, 1.f, GF_GELU);
}

// round 17
// speedup vs baseline: 1.8907x; 1.2128x over previous
#include <cuda_runtime.h>
#include <cuda_bf16.h>
#include <mma.h>
#include <cstdint>

using namespace nvcuda;

#define SQ 2048
#define NB 8
#define EMB 1024
#define RTOT (SQ*NB)
#define G4 (4*EMB)

#define GF_GELU   1
#define GF_CSKIP  2
#define GF_KCLAMP 4

typedef __nv_bfloat16 bf16;

// ---------------- device scratch (static; no allocation allowed) ----------------
__device__ float g_G    [(size_t)RTOT*G4];
__device__ float g_rnn  [(size_t)RTOT*EMB];
__device__ float g_hmid [(size_t)RTOT*EMB];
__device__ float g_vsc  [(size_t)RTOT*EMB];
__device__ float g_qpre [(size_t)RTOT*EMB];
__device__ float g_scores[(size_t)NB*SQ*SQ];
__device__ float g_h2   [(size_t)RTOT*EMB];
__device__ float g_res  [(size_t)RTOT*EMB];
__device__ float g_bias4[G4];
__device__ float g_op   [2*EMB];
__device__ float g_qsg  [EMB];
__device__ float g_ksg  [EMB];
__device__ float g_vsg  [EMB];
__device__ float g_hbuf [NB*EMB];
__device__ int   g_flags[128*32];   // one flag per block, 128B apart

__device__ __align__(256) bf16 g_xlnh [(size_t)RTOT*EMB];
__device__ __align__(256) bf16 g_xlnl [(size_t)RTOT*EMB];
__device__ __align__(256) bf16 g_Wihh [(size_t)G4*EMB];
__device__ __align__(256) bf16 g_Wihl [(size_t)G4*EMB];
__device__ __align__(256) bf16 g_hmidh[(size_t)RTOT*EMB];
__device__ __align__(256) bf16 g_hmidl[(size_t)RTOT*EMB];
__device__ __align__(256) bf16 g_qsch [(size_t)RTOT*EMB];
__device__ __align__(256) bf16 g_qscl [(size_t)RTOT*EMB];
__device__ __align__(256) bf16 g_ksch [(size_t)RTOT*EMB];
__device__ __align__(256) bf16 g_kscl [(size_t)RTOT*EMB];
__device__ __align__(256) bf16 g_xffh [(size_t)RTOT*EMB];
__device__ __align__(256) bf16 g_xffl [(size_t)RTOT*EMB];
__device__ __align__(256) bf16 g_vTh  [(size_t)NB*EMB*SQ];
__device__ __align__(256) bf16 g_vTl  [(size_t)NB*EMB*SQ];
__device__ __align__(256) bf16 g_wh   [(size_t)NB*SQ*SQ];
__device__ __align__(256) bf16 g_wl   [(size_t)NB*SQ*SQ];
__device__ __align__(256) bf16 g_qlWh [(size_t)EMB*EMB];
__device__ __align__(256) bf16 g_qlWl [(size_t)EMB*EMB];
__device__ __align__(256) bf16 g_bmWh [(size_t)EMB*EMB];
__device__ __align__(256) bf16 g_bmWl [(size_t)EMB*EMB];

__device__ __forceinline__ float sigm(float x){ return 1.0f/(1.0f + expf(-x)); }

// ---------------- prep ----------------
__global__ void prep_kernel(const float* __restrict__ bih, const float* __restrict__ bhh,
                            const float* __restrict__ qs, const float* __restrict__ ksp){
    int i = blockIdx.x*256 + threadIdx.x;
    if (i < G4) g_bias4[i] = bih[i] + bhh[i];
    if (i < EMB){
        g_qsg[i] = sigm(qs[i]); g_ksg[i] = sigm(ksp[i]);
        #pragma unroll
        for (int b = 0; b < NB; b++) g_hbuf[i + b*EMB] = 0.f;
    }
    if (i < 128*32) g_flags[i] = 0;
}

__global__ void op_gemm_kernel(const float* __restrict__ vsp, const float* __restrict__ opW,
                               const float* __restrict__ opb){
    __shared__ float vo[EMB];
    int tid = threadIdx.x;
    for (int i = tid; i < EMB; i += 256) vo[i] = sigm(vsp[i]);
    __syncthreads();
    int j = blockIdx.x*256 + tid;
    float acc = 0.f;
    const float* w = opW + (size_t)j*EMB;
    for (int e = 0; e < EMB; e += 4){
        float4 wv = *(const float4*)(w + e);
        acc += wv.x*vo[e] + wv.y*vo[e+1] + wv.z*vo[e+2] + wv.w*vo[e+3];
    }
    g_op[j] = acc + opb[j];
}

__global__ void vsg_kernel(){
    int i = blockIdx.x*256 + threadIdx.x;
    if (i < EMB) g_vsg[i] = sigm(g_op[EMB + i]) * tanhf(g_op[i]);
}

// fp32 -> bf16 hi/lo split
__global__ void split_kernel(const float* __restrict__ src, bf16* __restrict__ hi,
                             bf16* __restrict__ lo, int n){
    int i = blockIdx.x*256 + threadIdx.x;
    if (i < n){
        float v = src[i];
        bf16 h = __float2bfloat16(v);
        hi[i] = h; lo[i] = __float2bfloat16(v - __bfloat162float(h));
    }
}

// ---------------- block reductions ----------------
__device__ __forceinline__ float bsum(float v, float* buf){
    #pragma unroll
    for (int o = 16; o; o >>= 1) v += __shfl_xor_sync(0xffffffffu, v, o);
    int w = threadIdx.x >> 5;
    if ((threadIdx.x & 31) == 0) buf[w] = v;
    __syncthreads();
    if (threadIdx.x == 0){ float s = 0.f; for (int i = 0; i < 8; i++) s += buf[i]; buf[0] = s; }
    __syncthreads();
    float r = buf[0]; __syncthreads();
    return r;
}
__device__ __forceinline__ float bmax(float v, float* buf){
    #pragma unroll
    for (int o = 16; o; o >>= 1) v = fmaxf(v, __shfl_xor_sync(0xffffffffu, v, o));
    int w = threadIdx.x >> 5;
    if ((threadIdx.x & 31) == 0) buf[w] = v;
    __syncthreads();
    if (threadIdx.x == 0){ float s = buf[0]; for (int i = 1; i < 8; i++) s = fmaxf(s, buf[i]); buf[0] = s; }
    __syncthreads();
    float r = buf[0]; __syncthreads();
    return r;
}

// ---------------- layer norm: 3 outputs share stats; each may emit f32 and/or bf16 pair ----------------
__global__ void __launch_bounds__(256) ln_kernel(const float* __restrict__ in,
    float* f1, bf16* h1, bf16* l1, const float* g1, const float* b1, const float* s1,
    float* f2, bf16* h2, bf16* l2, const float* g2, const float* b2, const float* s2,
    float* f3, bf16* h3, bf16* l3, const float* g3, const float* b3, const float* s3){
    __shared__ float buf[8];
    size_t row = blockIdx.x;
    int tid = threadIdx.x, e = tid*4;
    float4 x = *(const float4*)(in + row*EMB + e);
    float m = bsum(x.x + x.y + x.z + x.w, buf) * (1.f/EMB);
    float d0 = x.x - m, d1 = x.y - m, d2 = x.z - m, d3 = x.w - m;
    float v = bsum(d0*d0 + d1*d1 + d2*d2 + d3*d3, buf) * (1.f/EMB);
    float rstd = rsqrtf(v + 1e-12f);
    #define EMIT(f,h,l,g,b,s) if (g){ \
        float4 gv = *(const float4*)((g)+e); float4 bv = *(const float4*)((b)+e); \
        float4 y; y.x = d0*rstd*gv.x + bv.x; y.y = d1*rstd*gv.y + bv.y; \
        y.z = d2*rstd*gv.z + bv.z; y.w = d3*rstd*gv.w + bv.w; \
        if (s){ float4 sv = *(const float4*)((s)+e); y.x*=sv.x; y.y*=sv.y; y.z*=sv.z; y.w*=sv.w; } \
        if (f) *(float4*)((f) + row*EMB + e) = y; \
        if (h){ bf16 p0=__float2bfloat16(y.x), p1=__float2bfloat16(y.y); \
                bf16 p2=__float2bfloat16(y.z), p3=__float2bfloat16(y.w); \
                *(__nv_bfloat162*)((h)+row*EMB+e)   = __halves2bfloat162(p0,p1); \
                *(__nv_bfloat162*)((h)+row*EMB+e+2) = __halves2bfloat162(p2,p3); \
                *(__nv_bfloat162*)((l)+row*EMB+e)   = __halves2bfloat162( \
                    __float2bfloat16(y.x-__bfloat162float(p0)), __float2bfloat16(y.y-__bfloat162float(p1))); \
                *(__nv_bfloat162*)((l)+row*EMB+e+2) = __halves2bfloat162( \
                    __float2bfloat16(y.z-__bfloat162float(p2)), __float2bfloat16(y.w-__bfloat162float(p3))); } }
    EMIT(f1,h1,l1,g1,b1,s1); EMIT(f2,h2,l2,g2,b2,s2); EMIT(f3,h3,l3,g3,b3,s3);
    #undef EMIT
}

// ---------------- causal softmax -> bf16 pair, zero-fill to 128 boundary ----------------
__global__ void __launch_bounds__(256) softmax_kernel(const float* __restrict__ sc,
        bf16* __restrict__ whi, bf16* __restrict__ wlo){
    __shared__ float buf[8];
    int blk = blockIdx.x;
    int s = blk & (SQ-1);
    const float* row = sc + (size_t)blk*SQ;
    int n = s + 1;
    int fill = ((s >> 7) + 1) << 7;
    float vals[8];
    float mx = -1e30f;
    int cnt = 0;
    for (int k = threadIdx.x; k < n; k += 256){ float v = row[k]; vals[cnt++] = v; mx = fmaxf(mx, v); }
    mx = bmax(mx, buf);
    float sm = 0.f;
    for (int i = 0; i < cnt; i++){ float e = expf(vals[i] - mx); vals[i] = e; sm += e; }
    sm = bsum(sm, buf);
    float inv = 1.f/sm;
    bf16* wh = whi + (size_t)blk*SQ;
    bf16* wl = wlo + (size_t)blk*SQ;
    cnt = 0;
    for (int k = threadIdx.x; k < fill; k += 256){
        float v = (k < n) ? vals[cnt++]*inv : 0.f;
        bf16 h = __float2bfloat16(v);
        wh[k] = h; wl[k] = __float2bfloat16(v - __bfloat162float(h));
    }
}

// ---------------- v transpose: [s][b][e] f32 -> [b][e][s] bf16 pair ----------------
__global__ void transpose_v(const float* __restrict__ vsc, bf16* __restrict__ vTh,
                            bf16* __restrict__ vTl){
    __shared__ float t[32][33];
    int b = blockIdx.z;
    int e0 = blockIdx.x*32, s0 = blockIdx.y*32;
    int x = threadIdx.x, y0 = threadIdx.y;
    for (int yy = y0; yy < 32; yy += 8)
        t[yy][x] = vsc[((size_t)(s0+yy)*NB + b)*EMB + e0 + x];
    __syncthreads();
    for (int yy = y0; yy < 32; yy += 8){
        float v = t[x][yy];
        size_t o = (size_t)b*EMB*SQ + (size_t)(e0+yy)*SQ + s0 + x;
        bf16 h = __float2bfloat16(v);
        vTh[o] = h; vTl[o] = __float2bfloat16(v - __bfloat162float(h));
    }
}

// ---------------- split-bf16 GEMM: C = alpha*(A@B^T)[+bias][gelu][+add] ----------------
// block tile 128x64x32, 8 warps of 32x32, 3-stage cp.async, 2 CTAs/SM
__device__ __forceinline__ void cpa16(bf16* dst, const bf16* src){
    uint32_t d = (uint32_t)__cvta_generic_to_shared(dst);
    asm volatile("cp.async.cg.shared.global [%0], [%1], 16;" :: "r"(d), "l"(src));
}

#define GEMM_SMEM 92160

__global__ void __launch_bounds__(256,2) gemm_kernel(
    const bf16* __restrict__ Ah, const bf16* __restrict__ Al, long long lda, long long sAz,
    const bf16* __restrict__ Bh, const bf16* __restrict__ Bl, long long ldb, long long sBz,
    float* __restrict__ C, long long ldc, long long sCz,
    int M, int N, int K,
    const float* __restrict__ bias, const float* __restrict__ addp,
    long long ldadd, long long sAddz, float alpha, int flags){
    extern __shared__ bf16 sm[];
    int m0 = blockIdx.y*128, n0 = blockIdx.x*64;
    if ((flags & GF_CSKIP) && n0 > m0 + 127) return;
    int Keff = (flags & GF_KCLAMP) ? min(K, m0 + 128) : K;
    int nkt = Keff >> 5;

    Ah += (size_t)blockIdx.z*sAz; Al += (size_t)blockIdx.z*sAz;
    Bh += (size_t)blockIdx.z*sBz; Bl += (size_t)blockIdx.z*sBz;
    C  += (size_t)blockIdx.z*sCz;
    if (addp) addp += (size_t)blockIdx.z*sAddz;

    int tid = threadIdx.x, warpId = tid >> 5, lane = tid & 31;
    int wm = warpId >> 1, wn = warpId & 1;

    wmma::fragment<wmma::accumulator,16,16,16,float> acc[2][2];
    #pragma unroll
    for (int i=0;i<2;i++)
        #pragma unroll
        for (int j=0;j<2;j++) wmma::fill_fragment(acc[i][j], 0.f);

    auto loadg = [&](int kt){
        int k0 = kt << 5, s = kt % 3;
        bf16* ash = sm + s*5120;
        bf16* asl = sm + 15360 + s*5120;
        bf16* bsh = sm + 30720 + s*2560;
        bf16* bsl = sm + 38400 + s*2560;
        #pragma unroll
        for (int i=0;i<2;i++){ int id = tid + i*256; int r = id>>2, c = (id&3)*8;
            cpa16(ash + r*40 + c, Ah + (size_t)(m0+r)*lda + k0 + c);
            cpa16(asl + r*40 + c, Al + (size_t)(m0+r)*lda + k0 + c); }
        { int r = tid>>2, c = (tid&3)*8;
            cpa16(bsh + r*40 + c, Bh + (size_t)(n0+r)*ldb + k0 + c);
            cpa16(bsl + r*40 + c, Bl + (size_t)(n0+r)*ldb + k0 + c); }
        asm volatile("cp.async.commit_group;");
    };

    loadg(0);
    if (nkt > 1) loadg(1);
    for (int kt = 0; kt < nkt; ++kt){
        if (kt == nkt-1) asm volatile("cp.async.wait_group 0;");
        else             asm volatile("cp.async.wait_group 1;");
        __syncthreads();
        if (kt + 2 < nkt) loadg(kt+2);
        int s = kt % 3;
        const bf16* ash = sm + s*5120;
        const bf16* asl = sm + 15360 + s*5120;
        const bf16* bsh = sm + 30720 + s*2560;
        const bf16* bsl = sm + 38400 + s*2560;
        #pragma unroll
        for (int ks = 0; ks < 2; ++ks){
            wmma::fragment<wmma::matrix_a,16,16,16,bf16,wmma::row_major> ah[2], al[2];
            wmma::fragment<wmma::matrix_b,16,16,16,bf16,wmma::col_major> bh[2], bl[2];
            #pragma unroll
            for (int im=0;im<2;im++){
                const bf16* p = ash + (wm*32+im*16)*40 + ks*16;
                wmma::load_matrix_sync(ah[im], p, 40);
                wmma::load_matrix_sync(al[im], asl + (wm*32+im*16)*40 + ks*16, 40);
            }
            #pragma unroll
            for (int in=0;in<2;in++){
                wmma::load_matrix_sync(bh[in], bsh + (wn*32+in*16)*40 + ks*16, 40);
                wmma::load_matrix_sync(bl[in], bsl + (wn*32+in*16)*40 + ks*16, 40);
            }
            #pragma unroll
            for (int im=0;im<2;im++)
                #pragma unroll
                for (int in=0;in<2;in++){
                    wmma::mma_sync(acc[im][in], ah[im], bh[in], acc[im][in]);
                    wmma::mma_sync(acc[im][in], ah[im], bl[in], acc[im][in]);
                    wmma::mma_sync(acc[im][in], al[im], bh[in], acc[im][in]);
                }
        }
        __syncthreads();
    }

    float* stg = (float*)sm + warpId*(32*36);
    #pragma unroll
    for (int im=0;im<2;im++)
        #pragma unroll
        for (int in=0;in<2;in++)
            wmma::store_matrix_sync(stg + im*16*36 + in*16, acc[im][in], 36, wmma::mem_row_major);
    __syncwarp();
    #pragma unroll 4
    for (int i = 0; i < 32; i++){
        float v = stg[i*36 + lane] * alpha;
        int grow = m0 + wm*32 + i, gcol = n0 + wn*32 + lane;
        if (bias) v += __ldg(bias + gcol);
        if (flags & GF_GELU) v = v * (1.f/(1.f + expf(-1.702f*v)));
        if (addp) v += addp[(size_t)grow*ldadd + gcol];
        C[(size_t)grow*ldc + gcol] = v;
    }
}

// ---------------- persistent LSTM: 128 blocks x 256 threads, Whh in registers ----------------
union __align__(16) F4U { float4 f; unsigned long long u[2]; };
union U64F2 { unsigned long long u; float2 f; };
__device__ __forceinline__ void ffma2(unsigned long long& acc, unsigned long long a, unsigned long long b){
    asm("fma.rn.f32x2 %0, %1, %2, %0;" : "+l"(acc) : "l"(a), "l"(b));
}

// hsm per-batch stride: 8 chunks x 132 floats (pad 4 per 128-chunk) + 4 = 1060
#define HBST 1060

__global__ void __launch_bounds__(256,1) lstm_kernel(const float* __restrict__ Whh){
    __shared__ float hsm[8*HBST];
    __shared__ float red[32*8];

    int tid = threadIdx.x;
    int bid = blockIdx.x;
    int c0 = bid*8;
    int row = tid >> 3;      // 0..31 = gate*8 + cell
    int ks  = tid & 7;       // k-slice of 128
    int gate = row >> 3, cell = row & 7;

    // Whh slice resident in registers: 128 floats
    float4 wreg[32];
    {
        const float* wp = Whh + ((size_t)(gate*1024 + c0 + cell))*1024 + ks*128;
        #pragma unroll
        for (int i = 0; i < 32; i++) wreg[i] = *(const float4*)(wp + i*4);
    }

    float cst = 0.f;
    int uj = tid >> 3, ub = tid & 7;   // update mapping (tid<64): cell, batch
    volatile int* myflag = (volatile int*)(g_flags + tid*32);

    for (int t = 0; t < SQ; ++t){
        float gi=0.f, gf=0.f, gg=0.f, go=0.f;
        if (tid < 64){
            const float* Gp = g_G + ((size_t)t*NB + ub)*G4 + c0 + uj;
            gi = __ldcs(Gp); gf = __ldcs(Gp+1024); gg = __ldcs(Gp+2048); go = __ldcs(Gp+3072);
        }
        // stage h (8x1024 f32) into padded smem
        #pragma unroll
        for (int it = 0; it < 8; it++){
            int idx = tid + it*256;           // float4 index 0..2047
            int b = idx >> 8, k4 = idx & 255;
            int k = k4*4, kk = k >> 7, rem = k & 127;
            float4 hv = __ldcg((const float4*)(g_hbuf + b*EMB + k));
            *(float4*)(hsm + b*HBST + kk*132 + rem) = hv;
        }
        __syncthreads();

        // dot: row x 8 batches over this thread's k-slice, w from registers
        U64F2 acc[8];
        #pragma unroll
        for (int b = 0; b < 8; b++) acc[b].f = make_float2(0.f, 0.f);
        const float* hbase = hsm + ks*132;
        #pragma unroll
        for (int i = 0; i < 32; i++){
            F4U wv; wv.f = wreg[i];
            #pragma unroll
            for (int b = 0; b < 8; b++){
                F4U hv = *(const F4U*)(hbase + b*HBST + i*4);
                ffma2(acc[b].u, wv.u[0], hv.u[0]);
                ffma2(acc[b].u, wv.u[1], hv.u[1]);
            }
        }
        // reduce across 8 k-slices (contiguous lanes) and publish
        #pragma unroll
        for (int b = 0; b < 8; b++){
            float s = acc[b].f.x + acc[b].f.y;
            s += __shfl_down_sync(0xffffffffu, s, 4, 8);
            s += __shfl_down_sync(0xffffffffu, s, 2, 8);
            s += __shfl_down_sync(0xffffffffu, s, 1, 8);
            if (ks == 0) red[row*8 + b] = s;
        }
        __syncthreads();

        if (tid < 64){
            float xi = red[(uj     )*8 + ub] + gi;
            float xf = red[(8 + uj )*8 + ub] + gf;
            float xg = red[(16 + uj)*8 + ub] + gg;
            float xo = red[(24 + uj)*8 + ub] + go;
            cst = sigm(xf)*cst + sigm(xi)*tanhf(xg);
            float hv = sigm(xo)*tanhf(cst);
            __stcg(g_hbuf + ub*EMB + c0 + uj, hv);
            g_rnn[(size_t)t*(NB*EMB) + ub*EMB + c0 + uj] = hv;
            __threadfence();
        }
        __syncthreads();
        // distributed flag barrier (release: fenced stores above; acquire: fence after poll)
        if (tid == 0) *(volatile int*)(g_flags + bid*32) = t + 1;
        if (tid < 128){
            while (*myflag <= t) {}
            __threadfence();
        }
        __syncthreads();
    }
}

// ---------------- host launch ----------------
extern "C" void kernel_launch(void* const* d_in, const int* in_sizes, int n_in,
                              void* d_out, int out_size){
    const float* inputs   = (const float*)d_in[0];
    const float* Wih      = (const float*)d_in[3];
    const float* Whh      = (const float*)d_in[4];
    const float* bih      = (const float*)d_in[5];
    const float* bhh      = (const float*)d_in[6];
    const float* lnstart_g=(const float*)d_in[7],  *lnstart_b=(const float*)d_in[8];
    const float* lnmem_g  =(const float*)d_in[9],  *lnmem_b  =(const float*)d_in[10];
    const float* lnmid_g  =(const float*)d_in[11], *lnmid_b  =(const float*)d_in[12];
    const float* lnff_g   =(const float*)d_in[13], *lnff_b   =(const float*)d_in[14];
    const float* lnxff_g  =(const float*)d_in[15], *lnxff_b  =(const float*)d_in[16];
    const float* qln_g    =(const float*)d_in[17], *qln_b    =(const float*)d_in[18];
    const float* qs       =(const float*)d_in[19], *ksp      =(const float*)d_in[20];
    const float* vsp      =(const float*)d_in[21];
    const float* opW      =(const float*)d_in[22], *opb      =(const float*)d_in[23];
    const float* qlW      =(const float*)d_in[24], *qlb      =(const float*)d_in[25];
    const float* boomW    =(const float*)d_in[26], *boomb    =(const float*)d_in[27];
    float* out = (float*)d_out;

    cudaFuncSetAttribute(gemm_kernel, cudaFuncAttributeMaxDynamicSharedMemorySize, GEMM_SMEM);

    float *p_G,*p_rnn,*p_hmid,*p_vsc,*p_qpre,*p_scores,*p_h2,*p_res,*p_bias4,*p_qsg,*p_ksg,*p_vsg;
    bf16 *p_xlnh,*p_xlnl,*p_Wihh,*p_Wihl,*p_hmidh,*p_hmidl,*p_qsch,*p_qscl,*p_ksch,*p_kscl;
    bf16 *p_xffh,*p_xffl,*p_vTh,*p_vTl,*p_wh,*p_wl,*p_qlWh,*p_qlWl,*p_bmWh,*p_bmWl;
    cudaGetSymbolAddress((void**)&p_G, g_G);
    cudaGetSymbolAddress((void**)&p_rnn, g_rnn);
    cudaGetSymbolAddress((void**)&p_hmid, g_hmid);
    cudaGetSymbolAddress((void**)&p_vsc, g_vsc);
    cudaGetSymbolAddress((void**)&p_qpre, g_qpre);
    cudaGetSymbolAddress((void**)&p_scores, g_scores);
    cudaGetSymbolAddress((void**)&p_h2, g_h2);
    cudaGetSymbolAddress((void**)&p_res, g_res);
    cudaGetSymbolAddress((void**)&p_bias4, g_bias4);
    cudaGetSymbolAddress((void**)&p_qsg, g_qsg);
    cudaGetSymbolAddress((void**)&p_ksg, g_ksg);
    cudaGetSymbolAddress((void**)&p_vsg, g_vsg);
    cudaGetSymbolAddress((void**)&p_xlnh, g_xlnh);  cudaGetSymbolAddress((void**)&p_xlnl, g_xlnl);
    cudaGetSymbolAddress((void**)&p_Wihh, g_Wihh);  cudaGetSymbolAddress((void**)&p_Wihl, g_Wihl);
    cudaGetSymbolAddress((void**)&p_hmidh, g_hmidh);cudaGetSymbolAddress((void**)&p_hmidl, g_hmidl);
    cudaGetSymbolAddress((void**)&p_qsch, g_qsch);  cudaGetSymbolAddress((void**)&p_qscl, g_qscl);
    cudaGetSymbolAddress((void**)&p_ksch, g_ksch);  cudaGetSymbolAddress((void**)&p_kscl, g_kscl);
    cudaGetSymbolAddress((void**)&p_xffh, g_xffh);  cudaGetSymbolAddress((void**)&p_xffl, g_xffl);
    cudaGetSymbolAddress((void**)&p_vTh, g_vTh);    cudaGetSymbolAddress((void**)&p_vTl, g_vTl);
    cudaGetSymbolAddress((void**)&p_wh, g_wh);      cudaGetSymbolAddress((void**)&p_wl, g_wl);
    cudaGetSymbolAddress((void**)&p_qlWh, g_qlWh);  cudaGetSymbolAddress((void**)&p_qlWl, g_qlWl);
    cudaGetSymbolAddress((void**)&p_bmWh, g_bmWh);  cudaGetSymbolAddress((void**)&p_bmWl, g_bmWl);

    prep_kernel<<<16,256>>>(bih, bhh, qs, ksp);
    op_gemm_kernel<<<8,256>>>(vsp, opW, opb);
    vsg_kernel<<<4,256>>>();
    split_kernel<<<(G4*EMB)/256,256>>>(Wih, p_Wihh, p_Wihl, G4*EMB);
    split_kernel<<<(EMB*EMB)/256,256>>>(qlW, p_qlWh, p_qlWl, EMB*EMB);
    split_kernel<<<(EMB*EMB)/256,256>>>(boomW, p_bmWh, p_bmWl, EMB*EMB);

    ln_kernel<<<RTOT,256>>>(inputs,
        nullptr, p_xlnh, p_xlnl, lnstart_g, lnstart_b, nullptr,
        nullptr, nullptr, nullptr, nullptr, nullptr, nullptr,
        nullptr, nullptr, nullptr, nullptr, nullptr, nullptr);
    gemm_kernel<<<dim3(64,128,1),256,GEMM_SMEM>>>(p_xlnh,p_xlnl,EMB,0, p_Wihh,p_Wihl,EMB,0,
        p_G,G4,0, RTOT,G4,EMB, p_bias4, nullptr,0,0, 1.f, 0);
    lstm_kernel<<<128,256>>>(Whh);
    ln_kernel<<<RTOT,256>>>(p_rnn,
        p_hmid, p_hmidh, p_hmidl, lnmid_g, lnmid_b, nullptr,
        nullptr, p_ksch, p_kscl, lnmem_g, lnmem_b, p_ksg,
        p_vsc, nullptr, nullptr, lnmem_g, lnmem_b, p_vsg);
    gemm_kernel<<<dim3(16,128,1),256,GEMM_SMEM>>>(p_hmidh,p_hmidl,EMB,0, p_qlWh,p_qlWl,EMB,0,
        p_qpre,EMB,0, RTOT,EMB,EMB, qlb, nullptr,0,0, 1.f, 0);
    ln_kernel<<<RTOT,256>>>(p_qpre,
        nullptr, p_qsch, p_qscl, qln_g, qln_b, p_qsg,
        nullptr, nullptr, nullptr, nullptr, nullptr, nullptr,
        nullptr, nullptr, nullptr, nullptr, nullptr, nullptr);
    gemm_kernel<<<dim3(32,16,8),256,GEMM_SMEM>>>(p_qsch,p_qscl,NB*EMB,EMB, p_ksch,p_kscl,NB*EMB,EMB,
        p_scores,SQ,(long long)SQ*SQ, SQ,SQ,EMB, nullptr, nullptr,0,0, 0.03125f, GF_CSKIP);
    softmax_kernel<<<RTOT,256>>>(p_scores, p_wh, p_wl);
    transpose_v<<<dim3(32,64,8),dim3(32,8)>>>(p_vsc, p_vTh, p_vTl);
    gemm_kernel<<<dim3(16,16,8),256,GEMM_SMEM>>>(p_wh,p_wl,SQ,(long long)SQ*SQ, p_vTh,p_vTl,SQ,(long long)EMB*SQ,
        p_h2,NB*EMB,EMB, SQ,EMB,SQ, nullptr, p_hmid,NB*EMB,EMB, 1.f, GF_KCLAMP);
    ln_kernel<<<RTOT,256>>>(p_h2,
        nullptr, p_xffh, p_xffl, lnxff_g, lnxff_b, nullptr,
        p_res, nullptr, nullptr, lnff_g, lnff_b, nullptr,
        nullptr, nullptr, nullptr, nullptr, nullptr, nullptr);
    gemm_kernel<<<dim3(16,128,1),256,GEMM_SMEM>>>(p_xffh,p_xffl,EMB,0, p_bmWh,p_bmWl,EMB,0,
        out,EMB,0, RTOT,EMB,EMB, boomb, p_res,EMB,0, 1.f, GF_GELU);
}